// round 16
// baseline (speedup 1.0000x reference)
#include <cuda_runtime.h>
#include <cuda_bf16.h>
#include <cstdint>
#include <cstddef>

#define BB 4
#define CC 256
#define CQ 64
#define NN 4096

// ---------------------------------------------------------------------------
// Scratch (device globals — allocation-free per harness rules)
// ---------------------------------------------------------------------------
__device__ __nv_bfloat16 g_xt[(size_t)BB * NN * CC];  // x^T [b][n][256] bf16, 8 MB
__device__ __nv_bfloat16 g_qt[(size_t)BB * NN * CQ];  // q^T [b][n][64], 2 MB
__device__ __nv_bfloat16 g_kt[(size_t)BB * NN * CQ];  // k^T [b][m][64], 2 MB
__device__ __nv_bfloat16 g_v [(size_t)BB * CC * NN];  // v   [b][c][n], 8 MB (scaled in place by stats)
__device__ __nv_bfloat16 g_e [(size_t)BB * NN * NN];  // E = e^{sT} [b][m][n], 128 MB

// ---------------------------------------------------------------------------
// helpers
// ---------------------------------------------------------------------------
__device__ __forceinline__ uint32_t smem_u32(const void* p) {
    uint32_t a;
    asm("{ .reg .u64 t; cvta.to.shared.u64 t, %1; cvt.u32.u64 %0, t; }" : "=r"(a) : "l"(p));
    return a;
}
__device__ __forceinline__ void cp16(uint32_t dst, const void* src) {
    asm volatile("cp.async.cg.shared.global [%0], [%1], 16;" :: "r"(dst), "l"(src));
}
#define CP_COMMIT() asm volatile("cp.async.commit_group;")
#define CP_WAIT(n)  asm volatile("cp.async.wait_group %0;" :: "n"(n))

__device__ __forceinline__ void mma_bf16(float* d, const uint32_t* a, const uint32_t* b) {
    asm volatile(
        "mma.sync.aligned.m16n8k16.row.col.f32.bf16.bf16.f32 "
        "{%0,%1,%2,%3}, {%4,%5,%6,%7}, {%8,%9}, {%0,%1,%2,%3};"
        : "+f"(d[0]), "+f"(d[1]), "+f"(d[2]), "+f"(d[3])
        : "r"(a[0]), "r"(a[1]), "r"(a[2]), "r"(a[3]), "r"(b[0]), "r"(b[1]));
}
__device__ __forceinline__ void ldsm4(uint32_t* r, uint32_t addr) {
    asm volatile("ldmatrix.sync.aligned.m8n8.x4.shared.b16 {%0,%1,%2,%3}, [%4];"
        : "=r"(r[0]), "=r"(r[1]), "=r"(r[2]), "=r"(r[3]) : "r"(addr));
}
// XOR swizzles: rows of 256B (16 c16), 512B (32 c16), 128B (8 c16)
#define SWZ(row, c16)    ((uint32_t)(row) * 256u + (((((uint32_t)(c16)) & 8u)  | ((((uint32_t)(c16)) ^ ((uint32_t)(row))) & 7u)) << 4))
#define SWZ512(row, c16) ((uint32_t)(row) * 512u + (((((uint32_t)(c16)) & 24u) | ((((uint32_t)(c16)) ^ ((uint32_t)(row))) & 7u)) << 4))
#define SWZ128(row, c16) ((uint32_t)(row) * 128u + (((((uint32_t)(c16)) ^ ((uint32_t)(row))) & 7u) << 4))

// ---------------------------------------------------------------------------
// convert_xt: x [b][c][n] fp32 -> xt [b][n][c] bf16  (transpose via smem tile)
// ---------------------------------------------------------------------------
__global__ __launch_bounds__(256) void convert_xt_kernel(const float* __restrict__ x)
{
    __shared__ __nv_bfloat16 T[64 * 80];
    const int tid = threadIdx.x;
    const int n0 = blockIdx.x * 64;
    const int c0 = blockIdx.y * 64;
    const int b  = blockIdx.z;
    const float* X = x + (size_t)b * CC * NN;
    __nv_bfloat16* XT = g_xt + (size_t)b * NN * CC;

    #pragma unroll
    for (int t = 0; t < 4; t++) {
        int idx = tid + t * 256;
        int row = idx >> 4, j = idx & 15;       // row: c local, j: group of 4 n
        float4 v = *(const float4*)&X[(size_t)(c0 + row) * NN + n0 + j * 4];
        T[(j * 4 + 0) * 80 + row] = __float2bfloat16(v.x);
        T[(j * 4 + 1) * 80 + row] = __float2bfloat16(v.y);
        T[(j * 4 + 2) * 80 + row] = __float2bfloat16(v.z);
        T[(j * 4 + 3) * 80 + row] = __float2bfloat16(v.w);
    }
    __syncthreads();
    #pragma unroll
    for (int t = 0; t < 2; t++) {
        int idx = tid + t * 256;
        int row = idx >> 3, c16 = idx & 7;      // row: n local, c16: c chunk
        uint4 val = *(uint4*)&T[row * 80 + c16 * 8];
        *(uint4*)&XT[(size_t)(n0 + row) * CC + c0 + c16 * 8] = val;
    }
}

// ---------------------------------------------------------------------------
// proj_mma: unified bf16 tensor projection.
//   mode 0: qt[n][o] = W_q . xt ; mode 1: kt ; mode 2..5: v rows (mode-2)*64
// Block: 256 thr (8 warps, 2m x 4n), tile M=64 x N=128 x K=256 one-shot.
// ---------------------------------------------------------------------------
#define PJ_A 0
#define PJ_B 32768
#define PJ_SMEM 98304

__global__ __launch_bounds__(256) void proj_mma_kernel(
    const float* __restrict__ wq, const float* __restrict__ bq,
    const float* __restrict__ wk, const float* __restrict__ bk,
    const float* __restrict__ wv, const float* __restrict__ bv)
{
    extern __shared__ char smem[];
    const uint32_t sb = smem_u32(smem);
    const int tid = threadIdx.x, wid = tid >> 5, lane = tid & 31;
    const int lr = lane >> 2, lc = lane & 3;
    const int mode = blockIdx.y;
    const int n0 = blockIdx.x * 128;
    const int b = blockIdx.z;

    const float *W, *bias;
    int mbase;
    if (mode == 0)      { W = wq; bias = bq; mbase = 0; }
    else if (mode == 1) { W = wk; bias = bk; mbase = 0; }
    else                { W = wv; bias = bv; mbase = (mode - 2) * 64; }

    const __nv_bfloat16* XT = g_xt + (size_t)b * NN * CC;

    // B: xt tile [128 n][256 k] via cp.async
    #pragma unroll
    for (int t = 0; t < 16; t++) {
        int idx = tid + t * 256;
        int row = idx >> 5, c16 = idx & 31;
        cp16(sb + PJ_B + SWZ512(row, c16), &XT[(size_t)(n0 + row) * CC + c16 * 8]);
    }
    CP_COMMIT();
    // A: W tile [64 m][256 k], fp32 -> bf16 convert into smem
    #pragma unroll
    for (int t = 0; t < 8; t++) {
        int idx = tid + t * 256;
        int row = idx >> 5, c16 = idx & 31;
        float4 a0 = *(const float4*)&W[(size_t)(mbase + row) * CC + c16 * 8];
        float4 a1 = *(const float4*)&W[(size_t)(mbase + row) * CC + c16 * 8 + 4];
        __nv_bfloat162 p0 = __floats2bfloat162_rn(a0.x, a0.y);
        __nv_bfloat162 p1 = __floats2bfloat162_rn(a0.z, a0.w);
        __nv_bfloat162 p2 = __floats2bfloat162_rn(a1.x, a1.y);
        __nv_bfloat162 p3 = __floats2bfloat162_rn(a1.z, a1.w);
        uint4 u = { *(uint32_t*)&p0, *(uint32_t*)&p1, *(uint32_t*)&p2, *(uint32_t*)&p3 };
        *(uint4*)(smem + PJ_A + SWZ512(row, c16)) = u;
    }
    CP_WAIT(0);
    __syncthreads();

    const int wm = wid & 1, wn = wid >> 1;
    float acc[2][4][4] = {};
    #pragma unroll
    for (int kk = 0; kk < 16; kk++) {
        uint32_t af[2][4], bfr[2][4];
        #pragma unroll
        for (int i = 0; i < 2; i++) {
            int row = wm * 32 + i * 16 + (lane & 15);
            int c16 = kk * 2 + (lane >> 4);
            ldsm4(af[i], sb + PJ_A + SWZ512(row, c16));
        }
        #pragma unroll
        for (int jg = 0; jg < 2; jg++) {
            int rown = wn * 32 + jg * 16 + (lane & 7) + ((lane >> 4) << 3);
            int c16  = kk * 2 + ((lane >> 3) & 1);
            ldsm4(bfr[jg], sb + PJ_B + SWZ512(rown, c16));
        }
        #pragma unroll
        for (int i = 0; i < 2; i++)
            #pragma unroll
            for (int j = 0; j < 4; j++)
                mma_bf16(acc[i][j], af[i], &bfr[j >> 1][(j & 1) * 2]);
    }
    __syncthreads();

    // stage D (+bias) as bf16 [64 m][136 n] in smem (reuses A region)
    __nv_bfloat16* Ds = (__nv_bfloat16*)smem;
    #pragma unroll
    for (int i = 0; i < 2; i++) {
        float b0 = __ldg(&bias[mbase + wm * 32 + i * 16 + lr]);
        float b1 = __ldg(&bias[mbase + wm * 32 + i * 16 + lr + 8]);
        #pragma unroll
        for (int j = 0; j < 4; j++) {
            int m = wm * 32 + i * 16 + lr;
            int n = wn * 32 + (j >> 1) * 16 + (j & 1) * 8 + 2 * lc;
            __nv_bfloat162 p0 = __floats2bfloat162_rn(acc[i][j][0] + b0, acc[i][j][1] + b0);
            __nv_bfloat162 p1 = __floats2bfloat162_rn(acc[i][j][2] + b1, acc[i][j][3] + b1);
            *(uint32_t*)&Ds[m * 136 + n]       = *(uint32_t*)&p0;
            *(uint32_t*)&Ds[(m + 8) * 136 + n] = *(uint32_t*)&p1;
        }
    }
    __syncthreads();

    if (mode >= 2) {
        // v: natural [c][n], coalesced 256B rows
        __nv_bfloat16* V = g_v + (size_t)b * CC * NN;
        #pragma unroll
        for (int t = 0; t < 4; t++) {
            int idx = tid + t * 256;
            int row = idx >> 4, c16 = idx & 15;
            uint4 u = *(uint4*)&Ds[row * 136 + c16 * 8];
            *(uint4*)&V[(size_t)(mbase + row) * NN + n0 + c16 * 8] = u;
        }
    } else {
        // q/k: transposed [n][64], coalesced 128B rows
        __nv_bfloat16* QT = (mode == 0 ? g_qt : g_kt) + (size_t)b * NN * CQ;
        #pragma unroll
        for (int t = 0; t < 4; t++) {
            int idx = tid + t * 256;
            int row = idx >> 3, c16 = idx & 7;   // row: n local, c16: o chunk
            uint32_t uu[4];
            #pragma unroll
            for (int e = 0; e < 4; e++) {
                __nv_bfloat162 pp;
                pp.x = Ds[(c16 * 8 + 2 * e)     * 136 + row];
                pp.y = Ds[(c16 * 8 + 2 * e + 1) * 136 + row];
                uu[e] = *(uint32_t*)&pp;
            }
            uint4 u = { uu[0], uu[1], uu[2], uu[3] };
            *(uint4*)&QT[(size_t)(n0 + row) * CQ + c16 * 8] = u;
        }
    }
}

// ---------------------------------------------------------------------------
// Stats: for n-block of 128, loop all m in 128-chunks:
//   sT[m][n] = sum_o kt[m][o] qt[n][o]; E = e^{sT} staged in smem -> coalesced
//   bf16 store to DRAM; Z[n] accumulated.
// Tail: scale v[0:256][nb:nb+128] by 1/Z in place.
// ldmatrix fragments on SWZ128 tiles. 512 threads, warps 4(m) x 4(n).
// ---------------------------------------------------------------------------
#define ST_QT 0
#define ST_KT 16384
#define ST_ES 49152
#define ST_RED 83968
#define ST_SMEM 86016

__global__ __launch_bounds__(512) void stats_kernel()
{
    extern __shared__ char smem[];
    const uint32_t sb = smem_u32(smem);
    const int tid = threadIdx.x, wid = tid >> 5, lane = tid & 31;
    const int lr = lane >> 2, lc = lane & 3;
    const int b = blockIdx.y;
    const int nb = blockIdx.x * 128;

    const __nv_bfloat16* QT = g_qt + (size_t)b * NN * CQ + (size_t)nb * CQ;
    const __nv_bfloat16* KT = g_kt + (size_t)b * NN * CQ;
    __nv_bfloat16* Eo = g_e + (size_t)b * NN * NN;

    #pragma unroll
    for (int t = 0; t < 2; t++) {
        int idx = tid + t * 512;
        int row = idx >> 3, c16 = idx & 7;
        cp16(sb + ST_QT + SWZ128(row, c16), &QT[(size_t)row * CQ + c16 * 8]);
        cp16(sb + ST_KT + SWZ128(row, c16), &KT[(size_t)row * CQ + c16 * 8]);
    }
    CP_COMMIT();

    const int wm = wid & 3, wn = wid >> 2;
    float Z[8];
    #pragma unroll
    for (int s = 0; s < 8; s++) Z[s] = 0.f;

    __nv_bfloat16* Es = (__nv_bfloat16*)(smem + ST_ES);   // [128 m][136 n]

    for (int ch = 0; ch < 32; ch++) {
        const int buf = ch & 1;
        if (ch + 1 < 32) {
            uint32_t bo = sb + ST_KT + ((ch + 1) & 1) * 16384;
            const __nv_bfloat16* src = KT + (size_t)(ch + 1) * 128 * CQ;
            #pragma unroll
            for (int t = 0; t < 2; t++) {
                int idx = tid + t * 512;
                int row = idx >> 3, c16 = idx & 7;
                cp16(bo + SWZ128(row, c16), &src[(size_t)row * CQ + c16 * 8]);
            }
            CP_COMMIT();
            CP_WAIT(1);
        } else {
            CP_WAIT(0);
        }
        __syncthreads();

        const uint32_t ktb = sb + ST_KT + buf * 16384;
        const uint32_t qtb = sb + ST_QT;

        float sa[2][4][4] = {};
        #pragma unroll
        for (int kk = 0; kk < 4; kk++) {
            uint32_t af[2][4], bfr[2][4];
            #pragma unroll
            for (int i = 0; i < 2; i++) {
                int row = wm * 32 + i * 16 + (lane & 15);
                int c16 = kk * 2 + (lane >> 4);
                ldsm4(af[i], ktb + SWZ128(row, c16));
            }
            #pragma unroll
            for (int jg = 0; jg < 2; jg++) {
                int rown = wn * 32 + jg * 16 + (lane & 7) + ((lane >> 4) << 3);
                int c16  = kk * 2 + ((lane >> 3) & 1);
                ldsm4(bfr[jg], qtb + SWZ128(rown, c16));
            }
            #pragma unroll
            for (int i = 0; i < 2; i++)
                #pragma unroll
                for (int j = 0; j < 4; j++)
                    mma_bf16(sa[i][j], af[i], &bfr[j >> 1][(j & 1) * 2]);
        }

        // exp -> stage bf16 in smem; accumulate Z
        #pragma unroll
        for (int i = 0; i < 2; i++)
            #pragma unroll
            for (int j = 0; j < 4; j++) {
                int m = wm * 32 + i * 16 + lr;
                int n = wn * 32 + (j >> 1) * 16 + (j & 1) * 8 + 2 * lc;
                float e0 = __expf(sa[i][j][0]);
                float e1 = __expf(sa[i][j][1]);
                float e2 = __expf(sa[i][j][2]);
                float e3 = __expf(sa[i][j][3]);
                __nv_bfloat162 p0 = __floats2bfloat162_rn(e0, e1);
                __nv_bfloat162 p1 = __floats2bfloat162_rn(e2, e3);
                *(uint32_t*)&Es[m * 136 + n]       = *(uint32_t*)&p0;
                *(uint32_t*)&Es[(m + 8) * 136 + n] = *(uint32_t*)&p1;
                Z[j * 2]     += e0 + e2;
                Z[j * 2 + 1] += e1 + e3;
            }
        __syncthreads();

        // coalesced E store: 128 rows x 256B
        const int mg = ch * 128;
        #pragma unroll
        for (int t = 0; t < 4; t++) {
            int idx = tid + t * 512;
            int row = idx >> 4, c16 = idx & 15;
            uint4 u = *(uint4*)&Es[row * 136 + c16 * 8];
            *(uint4*)&Eo[(size_t)(mg + row) * NN + nb + c16 * 8] = u;
        }
    }

    // reduce Z over lr lanes, then over 4 wm warps via smem
    #pragma unroll
    for (int s = 0; s < 8; s++) {
        float z = Z[s];
        z += __shfl_xor_sync(0xffffffffu, z, 4);
        z += __shfl_xor_sync(0xffffffffu, z, 8);
        z += __shfl_xor_sync(0xffffffffu, z, 16);
        Z[s] = z;
    }
    float* red = (float*)(smem + ST_RED);
    __syncthreads();
    if (lr == 0) {
        #pragma unroll
        for (int j = 0; j < 4; j++)
            #pragma unroll
            for (int s2 = 0; s2 < 2; s2++)
                red[wm * 128 + wn * 32 + (j >> 1) * 16 + (j & 1) * 8 + 2 * lc + s2] = Z[j * 2 + s2];
    }
    __syncthreads();
    // zinv for this block's 128 n-columns -> red[0..128)
    if (tid < 128) {
        float z = red[tid] + red[128 + tid] + red[256 + tid] + red[384 + tid];
        red[tid] = 1.f / z;
    }
    __syncthreads();

    // Tail: v[0:256][nb:nb+128] *= zinv in place.
    {
        __nv_bfloat16* V = g_v + (size_t)b * CC * NN;
        #pragma unroll
        for (int t = 0; t < 8; t++) {
            int idx = tid + t * 512;
            int row = idx >> 4, c16 = idx & 15;      // row: c, c16: 8-n chunk
            uint4 raw = *(uint4*)&V[(size_t)row * NN + nb + c16 * 8];
            __nv_bfloat162* h = (__nv_bfloat162*)&raw;
            const float* zp = &red[c16 * 8];
            #pragma unroll
            for (int e = 0; e < 4; e++) {
                float lo = __bfloat162float(h[e].x) * zp[2 * e];
                float hi = __bfloat162float(h[e].y) * zp[2 * e + 1];
                h[e] = __floats2bfloat162_rn(lo, hi);
            }
            *(uint4*)&V[(size_t)row * NN + nb + c16 * 8] = raw;
        }
    }
}

// ---------------------------------------------------------------------------
// Fused out (pure GEMM2): out[b][c][m] = gamma * sum_n vt[c][n] E[m][n] + x
// 256 threads / 8 warps, warp tile 64c x 64m (4 c-groups x 2 m-groups).
// Per warp-kstep: 8 ldsm.x4 : 32 MMA (was 6:16) — LDSM/issue pressure halved.
// Block tile 256c x 128m; K = 4096 n in 128-chunks, cp.async dbl-buffer.
// ---------------------------------------------------------------------------
#define F2_VA0 0
#define F2_VA1 65536
#define F2_EB0 131072
#define F2_EB1 163840
#define F2_SMEM 196608

__global__ __launch_bounds__(256) void fused_out_kernel(
    const float* __restrict__ x, const float* __restrict__ gamma,
    float* __restrict__ out)
{
    extern __shared__ char smem[];
    const uint32_t sb = smem_u32(smem);
    const int tid = threadIdx.x, wid = tid >> 5, lane = tid & 31;
    const int lr = lane >> 2, lc = lane & 3;
    const int b = blockIdx.y;
    const int m0 = blockIdx.x * 128;

    const __nv_bfloat16* Vt = g_v + (size_t)b * CC * NN;
    const __nv_bfloat16* E  = g_e + (size_t)b * NN * NN + (size_t)m0 * NN;

    // prologue: chunk 0
    {
        #pragma unroll
        for (int t = 0; t < 16; t++) {
            int idx = tid + t * 256, row = idx >> 4, c16 = idx & 15;
            cp16(sb + F2_VA0 + SWZ(row, c16), &Vt[(size_t)row * NN + c16 * 8]);
        }
        #pragma unroll
        for (int t = 0; t < 8; t++) {
            int idx = tid + t * 256, row = idx >> 4, c16 = idx & 15;
            cp16(sb + F2_EB0 + SWZ(row, c16), &E[(size_t)row * NN + c16 * 8]);
        }
        CP_COMMIT();
    }

    const int wc = wid & 3;    // 4 c-groups of 64
    const int wm = wid >> 2;   // 2 m-groups of 64
    float acc[4][8][4] = {};

    for (int ch = 0; ch < 32; ch++) {
        const int buf = ch & 1;
        if (ch + 1 < 32) {
            const int nch = (ch + 1) * 128;
            const uint32_t va = sb + (((ch + 1) & 1) ? F2_VA1 : F2_VA0);
            const uint32_t eb = sb + (((ch + 1) & 1) ? F2_EB1 : F2_EB0);
            #pragma unroll
            for (int t = 0; t < 16; t++) {
                int idx = tid + t * 256, row = idx >> 4, c16 = idx & 15;
                cp16(va + SWZ(row, c16), &Vt[(size_t)row * NN + nch + c16 * 8]);
            }
            #pragma unroll
            for (int t = 0; t < 8; t++) {
                int idx = tid + t * 256, row = idx >> 4, c16 = idx & 15;
                cp16(eb + SWZ(row, c16), &E[(size_t)row * NN + nch + c16 * 8]);
            }
            CP_COMMIT();
            CP_WAIT(1);
        } else {
            CP_WAIT(0);
        }
        __syncthreads();

        const uint32_t va = sb + (buf ? F2_VA1 : F2_VA0);
        const uint32_t eb = sb + (buf ? F2_EB1 : F2_EB0);

        #pragma unroll
        for (int kk = 0; kk < 8; kk++) {
            uint32_t af[4][4];
            #pragma unroll
            for (int i = 0; i < 4; i++) {
                int row = wc * 64 + i * 16 + (lane & 15);
                int c16 = kk * 2 + (lane >> 4);
                ldsm4(af[i], va + SWZ(row, c16));
            }
            uint32_t bfr[4][4];
            #pragma unroll
            for (int jg = 0; jg < 4; jg++) {
                int mrow = wm * 64 + jg * 16 + (lane & 7) + ((lane >> 4) << 3);
                int c16  = kk * 2 + ((lane >> 3) & 1);
                ldsm4(bfr[jg], eb + SWZ(mrow, c16));
            }
            #pragma unroll
            for (int i = 0; i < 4; i++)
                #pragma unroll
                for (int j = 0; j < 8; j++)
                    mma_bf16(acc[i][j], af[i], &bfr[j >> 1][(j & 1) * 2]);
        }
        __syncthreads();
    }

    // epilogue: out = gamma * acc + x
    const float g = gamma[0];
    #pragma unroll
    for (int i = 0; i < 4; i++)
        #pragma unroll
        for (int j = 0; j < 8; j++) {
            int c = wc * 64 + i * 16 + lr;
            int m = m0 + wm * 64 + j * 8 + 2 * lc;
            size_t g0 = (size_t)b * CC * NN + (size_t)c * NN + m;
            size_t g1 = g0 + (size_t)8 * NN;
            float2 x0 = *(const float2*)&x[g0];
            float2 x1 = *(const float2*)&x[g1];
            float2 o0 = { fmaf(g, acc[i][j][0], x0.x), fmaf(g, acc[i][j][1], x0.y) };
            float2 o1 = { fmaf(g, acc[i][j][2], x1.x), fmaf(g, acc[i][j][3], x1.y) };
            *(float2*)&out[g0] = o0;
            *(float2*)&out[g1] = o1;
        }
}

// ---------------------------------------------------------------------------
extern "C" void kernel_launch(void* const* d_in, const int* in_sizes, int n_in,
                              void* d_out, int out_size)
{
    const float* x     = (const float*)d_in[0];
    const float* wq    = (const float*)d_in[1];
    const float* bq    = (const float*)d_in[2];
    const float* wk    = (const float*)d_in[3];
    const float* bk    = (const float*)d_in[4];
    const float* wv    = (const float*)d_in[5];
    const float* bv    = (const float*)d_in[6];
    const float* gamma = (const float*)d_in[7];
    float* out = (float*)d_out;

    cudaFuncSetAttribute(proj_mma_kernel,  cudaFuncAttributeMaxDynamicSharedMemorySize, PJ_SMEM);
    cudaFuncSetAttribute(stats_kernel,     cudaFuncAttributeMaxDynamicSharedMemorySize, ST_SMEM);
    cudaFuncSetAttribute(fused_out_kernel, cudaFuncAttributeMaxDynamicSharedMemorySize, F2_SMEM);

    convert_xt_kernel<<<dim3(NN / 64, CC / 64, BB), 256>>>(x);

    proj_mma_kernel<<<dim3(NN / 128, 6, BB), 256, PJ_SMEM>>>(wq, bq, wk, bk, wv, bv);

    stats_kernel<<<dim3(NN / 128, BB), 512, ST_SMEM>>>();

    fused_out_kernel<<<dim3(NN / 128, BB), 256, F2_SMEM>>>(x, gamma, out);
}